// round 3
// baseline (speedup 1.0000x reference)
#include <cuda_runtime.h>

// Signature kernel (Goursat PDE) for 16x16 pairs of length-128, dim-8 paths.
// One CTA per (x,y) pair. Phase 1: RBF Gram + fused finite-diff into SMEM.
// Phase 2: anti-diagonal wavefront, one thread per grid row, state in
// registers, one __syncthreads + one shfl per diagonal.

#define LPATH 128   // path length
#define DIMS  8     // feature dim
#define DN    127   // diff matrix rows/cols
#define DSTR  128   // padded diff row stride (floats)
#define MROW  254   // PDE grid M = N = (LPATH-1)*2

// SMEM layout (floats):
//  sx   [128*8] = 1024
//  sy   [128*8] = 1024
//  xn   [128]
//  yn   [128]
//  kb   [4*128] = 512      (ring of K rows)
//  diff [127*128] = 16256  (finite diff / 4)
//  bnd  [2*8] = 16         (warp-seam exchange, double buffered)
#define SMEM_FLOATS (1024 + 1024 + 128 + 128 + 512 + 16256 + 16)

extern __shared__ float smem[];

__global__ void __launch_bounds__(256, 2)
sig_pde_kernel(const float* __restrict__ xs, const float* __restrict__ ys,
               float* __restrict__ out, int By)
{
    float* sx   = smem;
    float* sy   = sx + 1024;
    float* xn   = sy + 1024;
    float* yn   = xn + 128;
    float* kb   = yn + 128;          // [4][128]
    float* diff = kb + 512;          // [127][128]
    float* bnd  = diff + DN * DSTR;  // [2][8]

    const int t  = threadIdx.x;
    const int bx = blockIdx.y;   // index into xs
    const int by = blockIdx.x;   // index into ys

    // ---- load paths ----
    const float* gx = xs + (size_t)bx * (LPATH * DIMS);
    const float* gy = ys + (size_t)by * (LPATH * DIMS);
    #pragma unroll
    for (int i = t; i < LPATH * DIMS; i += 256) {
        sx[i] = gx[i];
        sy[i] = gy[i];
    }
    __syncthreads();

    // ---- squared norms ----
    if (t < 128) {
        float s = 0.f;
        #pragma unroll
        for (int k = 0; k < DIMS; k++) { float v = sx[t * DIMS + k]; s = fmaf(v, v, s); }
        xn[t] = s;
    } else {
        int c = t - 128;
        float s = 0.f;
        #pragma unroll
        for (int k = 0; k < DIMS; k++) { float v = sy[c * DIMS + k]; s = fmaf(v, v, s); }
        yn[c] = s;
    }
    __syncthreads();

    // ---- Phase 1: K rows (2 per iteration) + fused finite diff ----
    const int col  = t & 127;
    const int half = t >> 7;   // 0 or 1
    float yreg[DIMS];
    #pragma unroll
    for (int k = 0; k < DIMS; k++) yreg[k] = sy[col * DIMS + k];
    const float ynorm = yn[col];

    // exp(-sq/2) = exp2(-sq / (2*ln2))
    const float EXC = -0.72134752044448170367996234050095f;

    for (int i = 0; i < LPATH; i += 2) {
        int row = i + half;
        float dot = 0.f;
        #pragma unroll
        for (int k = 0; k < DIMS; k++) dot = fmaf(sx[row * DIMS + k], yreg[k], dot);
        float sq = xn[row] + ynorm - 2.f * dot;
        kb[(row & 3) * 128 + col] = exp2f(sq * EXC);
        __syncthreads();

        // produce diff rows: iter i==0 -> {0}; else {i-1, i}
        int dr = (i == 0) ? (half ? -1 : 0) : (i - 1 + half);
        if (dr >= 0 && col < DN) {
            float k11v = kb[((dr + 1) & 3) * 128 + col + 1];
            float k00v = kb[( dr      & 3) * 128 + col    ];
            float k10v = kb[((dr + 1) & 3) * 128 + col    ];
            float k01v = kb[( dr      & 3) * 128 + col + 1];
            diff[dr * DSTR + col] = 0.25f * ((k11v + k00v) - (k10v + k01v));
        }
        __syncthreads();  // protect kb ring slots reused 2 iterations later
    }

    // ---- Phase 2: Goursat PDE wavefront ----
    // thread t owns grid row t (rows 1..254 compute; row 0 stays boundary=1;
    // row 255 idles but participates in sync/shfl).
    const int row  = t;
    const int lane = t & 31;
    const int w    = t >> 5;

    int r = (row - 1) >> 1;
    if (r < 0)   r = 0;
    if (r > 126) r = 126;
    const float* drow = diff + r * DSTR;
    const bool rowok = (row >= 1) && (row <= MROW);

    float cur    = 1.f;   // K[row, j'] along the wavefront (boundary init)
    float nb_old = 1.f;   // neighbor's value from diagonal d-2 (= k00)

    for (int d = 2; d <= 2 * MROW; d++) {
        // publish this thread's diag d-1 value to warp seam slots
        if (lane == 31) bnd[(d & 1) * 8 + w] = cur;
        __syncthreads();

        float k10 = __shfl_up_sync(0xffffffffu, cur, 1);
        if (lane == 0) k10 = (w == 0) ? 1.f : bnd[(d & 1) * 8 + (w - 1)];

        float k00 = nb_old;  // neighbor, diagonal d-2
        nb_old = k10;

        int  j      = d - row;
        bool active = rowok && (j >= 1) && (j <= MROW);

        float inc = 0.f;
        if (active) inc = drow[(j - 1) >> 1];

        float i2 = inc * inc * (1.f / 12.f);
        float c1 = 1.f + 0.5f * inc + i2;
        float c2 = 1.f - i2;
        float k11 = (k10 + cur) * c1 - k00 * c2;
        if (active) cur = k11;
    }

    if (row == MROW) out[bx * By + by] = cur;
}

extern "C" void kernel_launch(void* const* d_in, const int* in_sizes, int n_in,
                              void* d_out, int out_size)
{
    const float* xs = (const float*)d_in[0];
    const float* ys = (const float*)d_in[1];
    float* out = (float*)d_out;

    int Bx = in_sizes[0] / (LPATH * DIMS);
    int By = in_sizes[1] / (LPATH * DIMS);

    size_t shbytes = SMEM_FLOATS * sizeof(float);
    cudaFuncSetAttribute(sig_pde_kernel,
                         cudaFuncAttributeMaxDynamicSharedMemorySize,
                         (int)shbytes);

    dim3 grid(By, Bx);
    sig_pde_kernel<<<grid, 256, shbytes>>>(xs, ys, out, By);
}

// round 4
// speedup vs baseline: 1.1172x; 1.1172x over previous
#include <cuda_runtime.h>

// Signature kernel (Goursat PDE) for 16x16 pairs of length-128, dim-8 paths.
// One CTA per (x,y) pair. Phase 1: RBF Gram + fused finite-diff into SMEM.
// Phase 2: anti-diagonal wavefront, one thread per grid row, state in
// registers, one __syncthreads + one shfl per diagonal.

#define LPATH 128   // path length
#define DIMS  8     // feature dim
#define DN    127   // diff matrix rows/cols
#define DSTR  128   // padded diff row stride (floats)
#define MROW  254   // PDE grid M = N = (LPATH-1)*2

// SMEM layout (floats):
//  sx   [128*8] = 1024
//  sy   [128*8] = 1024
//  xn   [128]
//  yn   [128]
//  kb   [4*128] = 512      (ring of K rows)
//  diff [127*128] = 16256  (finite diff / 4)
//  bnd  [2*8] = 16         (warp-seam exchange, double buffered)
#define SMEM_FLOATS (1024 + 1024 + 128 + 128 + 512 + 16256 + 16)

extern __shared__ float smem[];

__global__ void __launch_bounds__(256, 2)
sig_pde_kernel(const float* __restrict__ xs, const float* __restrict__ ys,
               float* __restrict__ out, int By)
{
    float* sx   = smem;
    float* sy   = sx + 1024;
    float* xn   = sy + 1024;
    float* yn   = xn + 128;
    float* kb   = yn + 128;          // [4][128]
    float* diff = kb + 512;          // [127][128]
    float* bnd  = diff + DN * DSTR;  // [2][8]

    const int t  = threadIdx.x;
    const int bx = blockIdx.y;   // index into xs
    const int by = blockIdx.x;   // index into ys

    // ---- load paths ----
    const float* gx = xs + (size_t)bx * (LPATH * DIMS);
    const float* gy = ys + (size_t)by * (LPATH * DIMS);
    #pragma unroll
    for (int i = t; i < LPATH * DIMS; i += 256) {
        sx[i] = gx[i];
        sy[i] = gy[i];
    }
    __syncthreads();

    // ---- squared norms ----
    if (t < 128) {
        float s = 0.f;
        #pragma unroll
        for (int k = 0; k < DIMS; k++) { float v = sx[t * DIMS + k]; s = fmaf(v, v, s); }
        xn[t] = s;
    } else {
        int c = t - 128;
        float s = 0.f;
        #pragma unroll
        for (int k = 0; k < DIMS; k++) { float v = sy[c * DIMS + k]; s = fmaf(v, v, s); }
        yn[c] = s;
    }
    __syncthreads();

    // ---- Phase 1: K rows (2 per iteration) + fused finite diff ----
    const int col  = t & 127;
    const int half = t >> 7;   // 0 or 1
    float yreg[DIMS];
    #pragma unroll
    for (int k = 0; k < DIMS; k++) yreg[k] = sy[col * DIMS + k];
    const float ynorm = yn[col];

    // exp(-sq/2) = exp2(-sq / (2*ln2))
    const float EXC = -0.72134752044448170367996234050095f;

    for (int i = 0; i < LPATH; i += 2) {
        int row = i + half;
        float dot = 0.f;
        #pragma unroll
        for (int k = 0; k < DIMS; k++) dot = fmaf(sx[row * DIMS + k], yreg[k], dot);
        float sq = xn[row] + ynorm - 2.f * dot;
        kb[(row & 3) * 128 + col] = exp2f(sq * EXC);
        __syncthreads();

        // produce diff rows: iter i==0 -> {0}; else {i-1, i}
        int dr = (i == 0) ? (half ? -1 : 0) : (i - 1 + half);
        if (dr >= 0 && col < DN) {
            float k11v = kb[((dr + 1) & 3) * 128 + col + 1];
            float k00v = kb[( dr      & 3) * 128 + col    ];
            float k10v = kb[((dr + 1) & 3) * 128 + col    ];
            float k01v = kb[( dr      & 3) * 128 + col + 1];
            diff[dr * DSTR + col] = 0.25f * ((k11v + k00v) - (k10v + k01v));
        }
        __syncthreads();  // protect kb ring slots reused 2 iterations later
    }

    // ---- Phase 2: Goursat PDE wavefront ----
    // thread t owns grid row t (rows 1..254 compute; row 0 stays boundary=1;
    // row 255 idles but participates in sync/shfl).
    const int row  = t;
    const int lane = t & 31;
    const int w    = t >> 5;

    int r = (row - 1) >> 1;
    if (r < 0)   r = 0;
    if (r > 126) r = 126;
    const float* drow = diff + r * DSTR;
    const bool rowok = (row >= 1) && (row <= MROW);

    float cur    = 1.f;   // K[row, j'] along the wavefront (boundary init)
    float nb_old = 1.f;   // neighbor's value from diagonal d-2 (= k00)

    for (int d = 2; d <= 2 * MROW; d++) {
        // publish this thread's diag d-1 value to warp seam slots
        if (lane == 31) bnd[(d & 1) * 8 + w] = cur;
        __syncthreads();

        float k10 = __shfl_up_sync(0xffffffffu, cur, 1);
        if (lane == 0) k10 = (w == 0) ? 1.f : bnd[(d & 1) * 8 + (w - 1)];

        float k00 = nb_old;  // neighbor, diagonal d-2
        nb_old = k10;

        int  j      = d - row;
        bool active = rowok && (j >= 1) && (j <= MROW);

        float inc = 0.f;
        if (active) inc = drow[(j - 1) >> 1];

        float i2 = inc * inc * (1.f / 12.f);
        float c1 = 1.f + 0.5f * inc + i2;
        float c2 = 1.f - i2;
        float k11 = (k10 + cur) * c1 - k00 * c2;
        if (active) cur = k11;
    }

    if (row == MROW) out[bx * By + by] = cur;
}

extern "C" void kernel_launch(void* const* d_in, const int* in_sizes, int n_in,
                              void* d_out, int out_size)
{
    const float* xs = (const float*)d_in[0];
    const float* ys = (const float*)d_in[1];
    float* out = (float*)d_out;

    int Bx = in_sizes[0] / (LPATH * DIMS);
    int By = in_sizes[1] / (LPATH * DIMS);

    size_t shbytes = SMEM_FLOATS * sizeof(float);
    cudaFuncSetAttribute(sig_pde_kernel,
                         cudaFuncAttributeMaxDynamicSharedMemorySize,
                         (int)shbytes);

    dim3 grid(By, Bx);
    sig_pde_kernel<<<grid, 256, shbytes>>>(xs, ys, out, By);
}